// round 9
// baseline (speedup 1.0000x reference)
#include <cuda_runtime.h>
#include <cuda_bf16.h>
#include <cstdint>

#define NN   50000
#define EE   800000
#define EP   200000
#define CC   128
#define NBLK 49                      // ceil(NN/1024)
#define GEMM_GRID ((NN + 127) / 128) // 391

// ------------------------- static device scratch -------------------------
__device__ int   g_is64;
__device__ int   g_src[EE];
__device__ int   g_dst[EE];
__device__ int   g_ps[EP];
__device__ int   g_pd[EP];
__device__ int   g_deg[NN];
__device__ int   g_off[NN + 1];
__device__ int   g_cur[NN];
__device__ int   g_bsum[64];
__device__ int   g_boff[64];
__device__ int   g_csr[EE];
__device__ float g_h[NN * CC];
__device__ float g_z[NN * CC];
// bf16 hi/lo operand buffers
__device__ __nv_bfloat16 g_xh[NN * CC];
__device__ __nv_bfloat16 g_xl[NN * CC];
__device__ __nv_bfloat16 g_aggh[NN * CC];
__device__ __nv_bfloat16 g_aggl[NN * CC];
__device__ __nv_bfloat16 g_hh[NN * CC];
__device__ __nv_bfloat16 g_hl[NN * CC];
__device__ __nv_bfloat16 g_w1h[2 * CC * CC];
__device__ __nv_bfloat16 g_w1l[2 * CC * CC];
__device__ __nv_bfloat16 g_w2h[2 * CC * CC];
__device__ __nv_bfloat16 g_w2l[2 * CC * CC];

// ------------------------- helpers -------------------------
__device__ __forceinline__ void cvt_hilo(float v, uint32_t& h, uint32_t& l) {
    __nv_bfloat16 hb = __float2bfloat16_rn(v);
    __nv_bfloat16 lb = __float2bfloat16_rn(v - __bfloat162float(hb));
    h = (uint32_t)__bfloat16_as_ushort(hb);
    l = (uint32_t)__bfloat16_as_ushort(lb);
}
__device__ __forceinline__ void cp16(uint32_t dst, const void* src, int sz) {
    asm volatile("cp.async.cg.shared.global [%0], [%1], 16, %2;"
                 :: "r"(dst), "l"(src), "r"(sz) : "memory");
}
#define CP_COMMIT() asm volatile("cp.async.commit_group;" ::: "memory")
__device__ __forceinline__ void ldsm4(uint32_t* r, uint32_t addr) {
    asm volatile("ldmatrix.sync.aligned.m8n8.x4.shared.b16 {%0,%1,%2,%3}, [%4];"
                 : "=r"(r[0]), "=r"(r[1]), "=r"(r[2]), "=r"(r[3]) : "r"(addr));
}
__device__ __forceinline__ void ldsm4t(uint32_t* r, uint32_t addr) {
    asm volatile("ldmatrix.sync.aligned.m8n8.x4.trans.shared.b16 {%0,%1,%2,%3}, [%4];"
                 : "=r"(r[0]), "=r"(r[1]), "=r"(r[2]), "=r"(r[3]) : "r"(addr));
}
__device__ __forceinline__ void mma_bf16(float* d, const uint32_t* a,
                                         uint32_t b0, uint32_t b1) {
    asm volatile(
        "mma.sync.aligned.m16n8k16.row.col.f32.bf16.bf16.f32 "
        "{%0,%1,%2,%3}, {%4,%5,%6,%7}, {%8,%9}, {%0,%1,%2,%3};"
        : "+f"(d[0]), "+f"(d[1]), "+f"(d[2]), "+f"(d[3])
        : "r"(a[0]), "r"(a[1]), "r"(a[2]), "r"(a[3]), "r"(b0), "r"(b1));
}

// ------------------------- index dtype probe -------------------------
__global__ void detect_kernel(const int* ei) {
    if (threadIdx.x == 0 && blockIdx.x == 0) {
        int ok64 = 1;
        for (int i = 0; i < 64; i++)
            if (ei[2 * i + 1] != 0) { ok64 = 0; break; }
        g_is64 = ok64;
    }
}

// zero deg + convert pred edges (fused)
__global__ void zero_pred_kernel(const int* pe) {
    int i = blockIdx.x * blockDim.x + threadIdx.x;
    if (i < NN) g_deg[i] = 0;
    if (i < EP) {
        if (g_is64) {
            const long long* q = (const long long*)pe;
            g_ps[i] = (int)q[i];
            g_pd[i] = (int)q[EP + i];
        } else {
            g_ps[i] = pe[i];
            g_pd[i] = pe[EP + i];
        }
    }
}

// convert edges + histogram (fused)
__global__ void edges_hist_kernel(const int* ei) {
    int e = blockIdx.x * blockDim.x + threadIdx.x;
    if (e >= EE) return;
    int s, d;
    if (g_is64) {
        const long long* q = (const long long*)ei;
        s = (int)q[e];
        d = (int)q[EE + e];
    } else {
        s = ei[e];
        d = ei[EE + e];
    }
    g_src[e] = s;
    g_dst[e] = d;
    atomicAdd(&g_deg[d], 1);
}

// ------------------------- multi-block scan -------------------------
__global__ void scan1_kernel() {
    __shared__ int wsum[32];
    int b = blockIdx.x, t = threadIdx.x, i = b * 1024 + t;
    int lane = t & 31, w = t >> 5;
    int v = (i < NN) ? g_deg[i] : 0;
    int x = v;
    #pragma unroll
    for (int o = 1; o < 32; o <<= 1) {
        int y = __shfl_up_sync(0xffffffffu, x, o);
        if (lane >= o) x += y;
    }
    if (lane == 31) wsum[w] = x;
    __syncthreads();
    if (w == 0) {
        int s = wsum[lane];
        #pragma unroll
        for (int o = 1; o < 32; o <<= 1) {
            int y = __shfl_up_sync(0xffffffffu, s, o);
            if (lane >= o) s += y;
        }
        wsum[lane] = s;
    }
    __syncthreads();
    int incl = x + (w ? wsum[w - 1] : 0);
    if (i < NN) g_off[i] = incl - v;
    if (t == 1023) g_bsum[b] = incl;
}

__global__ void scan_top_kernel() {
    if (threadIdx.x == 0 && blockIdx.x == 0) {
        int run = 0;
        for (int b = 0; b < NBLK; b++) { g_boff[b] = run; run += g_bsum[b]; }
        g_off[NN] = run;
    }
}

__global__ void scan_add_kernel() {
    int b = blockIdx.x, i = b * 1024 + threadIdx.x;
    if (i < NN) {
        int o = g_off[i] + g_boff[b];
        g_off[i] = o;
        g_cur[i] = o;
    }
}

__global__ void scatter_kernel() {
    int e = blockIdx.x * blockDim.x + threadIdx.x;
    if (e < EE) {
        int p = atomicAdd(&g_cur[g_dst[e]], 1);
        g_csr[p] = g_src[e];
    }
}

// ------------------------- fp32 -> hi/lo bf16 converters -------------------------
__global__ void cvt_x_kernel(const float4* __restrict__ x) {
    int i = blockIdx.x * blockDim.x + threadIdx.x;   // float4 index
    if (i >= NN * 32) return;
    float4 v = x[i];
    uint32_t h0, l0, h1, l1, h2, l2, h3, l3;
    cvt_hilo(v.x, h0, l0); cvt_hilo(v.y, h1, l1);
    cvt_hilo(v.z, h2, l2); cvt_hilo(v.w, h3, l3);
    uint2 uh, ul;
    uh.x = h0 | (h1 << 16); uh.y = h2 | (h3 << 16);
    ul.x = l0 | (l1 << 16); ul.y = l2 | (l3 << 16);
    ((uint2*)g_xh)[i] = uh;
    ((uint2*)g_xl)[i] = ul;
}

// combined W[256][128]: rows 0..127 = Wl, 128..255 = Wr (per layer)
__global__ void cvt_w_kernel(const float* __restrict__ W1l, const float* __restrict__ W1r,
                             const float* __restrict__ W2l, const float* __restrict__ W2r) {
    int idx = blockIdx.x * blockDim.x + threadIdx.x;   // 0 .. 2*256*128-1
    if (idx >= 2 * 2 * CC * CC) return;
    int layer = idx >> 15;
    int rem = idx & 32767;
    int k = rem >> 7, n = rem & 127;
    float v;
    if (layer == 0) v = (k < CC) ? W1l[k * CC + n] : W1r[(k - CC) * CC + n];
    else            v = (k < CC) ? W2l[k * CC + n] : W2r[(k - CC) * CC + n];
    uint32_t h, l;
    cvt_hilo(v, h, l);
    if (layer == 0) {
        g_w1h[rem] = __ushort_as_bfloat16((unsigned short)h);
        g_w1l[rem] = __ushort_as_bfloat16((unsigned short)l);
    } else {
        g_w2h[rem] = __ushort_as_bfloat16((unsigned short)h);
        g_w2l[rem] = __ushort_as_bfloat16((unsigned short)l);
    }
}

// ------------------------- mean aggregation -> hi/lo bf16 -------------------------
__global__ void agg_kernel(const float4* __restrict__ in) {
    int node = blockIdx.x * (blockDim.x >> 5) + (threadIdx.x >> 5);
    int lane = threadIdx.x & 31;
    if (node >= NN) return;
    int s = g_off[node];
    int d = g_deg[node];
    float4 acc = make_float4(0.f, 0.f, 0.f, 0.f);
    for (int base = 0; base < d; base += 32) {
        int cnt = min(32, d - base);
        int myidx = (lane < cnt) ? g_csr[s + base + lane] : 0;
        for (int i = 0; i < cnt; i++) {
            int src = __shfl_sync(0xffffffffu, myidx, i);
            float4 v = in[src * 32 + lane];
            acc.x += v.x; acc.y += v.y; acc.z += v.z; acc.w += v.w;
        }
    }
    float inv = (d > 0) ? (1.0f / (float)d) : 0.0f;
    acc.x *= inv; acc.y *= inv; acc.z *= inv; acc.w *= inv;
    uint32_t h0, l0, h1, l1, h2, l2, h3, l3;
    cvt_hilo(acc.x, h0, l0); cvt_hilo(acc.y, h1, l1);
    cvt_hilo(acc.z, h2, l2); cvt_hilo(acc.w, h3, l3);
    uint2 uh, ul;
    uh.x = h0 | (h1 << 16); uh.y = h2 | (h3 << 16);
    ul.x = l0 | (l1 << 16); ul.y = l2 | (l3 << 16);
    ((uint2*)g_aggh)[node * 32 + lane] = uh;
    ((uint2*)g_aggl)[node * 32 + lane] = ul;
}

// ------------------------- pipelined bf16 hi/lo GEMM -------------------------
// out = relu?([A1|A2] @ W + b), K = 256 in 8 chunks of 32, 2-stage cp.async.
// smem per stage: AH[128x40] AL BH[32x136] BL (bf16, padded strides).
#define A_ST 40
#define B_ST 136
#define STG_AH 0
#define STG_AL 10240
#define STG_BH 20480
#define STG_BL 29184
#define STAGE_SZ 37888
#define GEMM_SMEM (2 * STAGE_SZ)

__global__ __launch_bounds__(256)
void gemm_bf16_kernel(const __nv_bfloat16* __restrict__ A1h, const __nv_bfloat16* __restrict__ A1l,
                      const __nv_bfloat16* __restrict__ A2h, const __nv_bfloat16* __restrict__ A2l,
                      const __nv_bfloat16* __restrict__ Wh,  const __nv_bfloat16* __restrict__ Wl,
                      const float* __restrict__ bias, float* __restrict__ outf,
                      __nv_bfloat16* __restrict__ outh, __nv_bfloat16* __restrict__ outl,
                      int do_relu) {
    extern __shared__ char sm[];
    uint32_t smb = (uint32_t)__cvta_generic_to_shared(sm);

    int tid = threadIdx.x;
    int wid = tid >> 5, lane = tid & 31;
    int warpM = wid & 3;
    int warpN = wid >> 2;
    int rowBase = blockIdx.x * 128;

    // prefetch thread mapping
    int ar = tid >> 2, aq = tid & 3;          // A: rows (+128 on 2nd it), 4x16B per row
    int br = tid >> 4, bq = tid & 15;         // B: 16 rows per it, 16x16B per row

    float acc[64];
    #pragma unroll
    for (int i = 0; i < 64; i++) acc[i] = 0.f;

    // ---- prefetch lambda-ish macro ----
    #define PREFETCH(c, stg) do {                                              \
        const __nv_bfloat16* Ah_ = ((c) < 4) ? A1h : A2h;                      \
        const __nv_bfloat16* Al_ = ((c) < 4) ? A1l : A2l;                      \
        int k0a = ((c) & 3) * 32;                                              \
        int k0w = (c) * 32;                                                    \
        uint32_t sb_ = smb + (stg) * STAGE_SZ;                                 \
        _Pragma("unroll")                                                      \
        for (int it = 0; it < 2; it++) {                                       \
            int r = it * 64 + ar;                                              \
            int grow = rowBase + r;                                            \
            int ok = (grow < NN) ? 16 : 0;                                     \
            long goff = (long)min(grow, NN - 1) * CC + k0a + aq * 8;           \
            cp16(sb_ + STG_AH + r * 80 + aq * 16, Ah_ + goff, ok);             \
            cp16(sb_ + STG_AL + r * 80 + aq * 16, Al_ + goff, ok);             \
        }                                                                      \
        _Pragma("unroll")                                                      \
        for (int it = 0; it < 2; it++) {                                       \
            int r = it * 16 + br;                                              \
            long goff = (long)(k0w + r) * CC + bq * 8;                         \
            cp16(sb_ + STG_BH + r * 272 + bq * 16, Wh + goff, 16);             \
            cp16(sb_ + STG_BL + r * 272 + bq * 16, Wl + goff, 16);             \
        }                                                                      \
    } while (0)

    PREFETCH(0, 0);
    CP_COMMIT();

    int r16 = lane & 15, cb = lane >> 4;
    int browL = (lane & 7) + ((lane >> 3) & 1) * 8;

    for (int c = 0; c < 8; c++) {
        int stg = c & 1;
        if (c < 7) { PREFETCH(c + 1, stg ^ 1); CP_COMMIT(); }
        if (c < 7) asm volatile("cp.async.wait_group 1;" ::: "memory");
        else       asm volatile("cp.async.wait_group 0;" ::: "memory");
        __syncthreads();

        uint32_t sb = smb + stg * STAGE_SZ;
        #pragma unroll
        for (int ks = 0; ks < 2; ks++) {
            int kk = ks * 16;
            uint32_t ah[2][4], al[2][4];
            #pragma unroll
            for (int mf = 0; mf < 2; mf++) {
                uint32_t off = (uint32_t)(warpM * 32 + mf * 16 + r16) * 80
                             + (uint32_t)(kk + cb * 8) * 2;
                ldsm4(ah[mf], sb + STG_AH + off);
                ldsm4(al[mf], sb + STG_AL + off);
            }
            int brow = kk + browL;
            #pragma unroll
            for (int np = 0; np < 4; np++) {
                int n0 = warpN * 64 + np * 16 + cb * 8;
                uint32_t boff = (uint32_t)brow * 272 + (uint32_t)n0 * 2;
                uint32_t bh[4], bl[4];
                ldsm4t(bh, sb + STG_BH + boff);
                ldsm4t(bl, sb + STG_BL + boff);
                #pragma unroll
                for (int mf = 0; mf < 2; mf++) {
                    float* d0 = &acc[(mf * 8 + np * 2 + 0) * 4];
                    float* d1 = &acc[(mf * 8 + np * 2 + 1) * 4];
                    mma_bf16(d0, ah[mf], bh[0], bh[1]);
                    mma_bf16(d1, ah[mf], bh[2], bh[3]);
                    mma_bf16(d0, ah[mf], bl[0], bl[1]);
                    mma_bf16(d1, ah[mf], bl[2], bl[3]);
                    mma_bf16(d0, al[mf], bh[0], bh[1]);
                    mma_bf16(d1, al[mf], bh[2], bh[3]);
                }
            }
        }
        __syncthreads();
    }

    // epilogue: bias + relu, fp32 + optional hi/lo bf16
    int r = lane >> 2;
    int cb2 = (lane & 3) * 2;
    #pragma unroll
    for (int mf = 0; mf < 2; mf++) {
        int row0 = rowBase + warpM * 32 + mf * 16 + r;
        #pragma unroll
        for (int np = 0; np < 4; np++) {
            #pragma unroll
            for (int half = 0; half < 2; half++) {
                int col = warpN * 64 + np * 16 + half * 8 + cb2;
                const float* d = &acc[(mf * 8 + np * 2 + half) * 4];
                float bx = __ldg(&bias[col]);
                float by = __ldg(&bias[col + 1]);
                float2 o0, o1;
                o0.x = d[0] + bx; o0.y = d[1] + by;
                o1.x = d[2] + bx; o1.y = d[3] + by;
                if (do_relu) {
                    o0.x = fmaxf(o0.x, 0.f); o0.y = fmaxf(o0.y, 0.f);
                    o1.x = fmaxf(o1.x, 0.f); o1.y = fmaxf(o1.y, 0.f);
                }
                if (row0 < NN) {
                    *(float2*)&outf[row0 * CC + col] = o0;
                    if (outh) {
                        uint32_t hx, lx, hy, ly;
                        cvt_hilo(o0.x, hx, lx); cvt_hilo(o0.y, hy, ly);
                        *(uint32_t*)&outh[row0 * CC + col] = hx | (hy << 16);
                        *(uint32_t*)&outl[row0 * CC + col] = lx | (ly << 16);
                    }
                }
                if (row0 + 8 < NN) {
                    *(float2*)&outf[(row0 + 8) * CC + col] = o1;
                    if (outh) {
                        uint32_t hx, lx, hy, ly;
                        cvt_hilo(o1.x, hx, lx); cvt_hilo(o1.y, hy, ly);
                        *(uint32_t*)&outh[(row0 + 8) * CC + col] = hx | (hy << 16);
                        *(uint32_t*)&outl[(row0 + 8) * CC + col] = lx | (ly << 16);
                    }
                }
            }
        }
    }
    #undef PREFETCH
}

// ------------------------- link prediction dot -------------------------
__global__ void dot_kernel(const float4* __restrict__ z, float* __restrict__ out) {
    int e = blockIdx.x * (blockDim.x >> 5) + (threadIdx.x >> 5);
    int lane = threadIdx.x & 31;
    if (e >= EP) return;
    int a = g_ps[e];
    int b = g_pd[e];
    float4 va = z[a * 32 + lane];
    float4 vb = z[b * 32 + lane];
    float s = va.x * vb.x + va.y * vb.y + va.z * vb.z + va.w * vb.w;
    #pragma unroll
    for (int o = 16; o > 0; o >>= 1) s += __shfl_xor_sync(0xffffffffu, s, o);
    if (lane == 0) out[e] = s;
}

// ------------------------- launch -------------------------
extern "C" void kernel_launch(void* const* d_in, const int* in_sizes, int n_in,
                              void* d_out, int out_size) {
    const float* x   = (const float*)d_in[0];
    const float* W1l = (const float*)d_in[1];
    const float* b1  = (const float*)d_in[2];
    const float* W1r = (const float*)d_in[3];
    const float* W2l = (const float*)d_in[4];
    const float* b2  = (const float*)d_in[5];
    const float* W2r = (const float*)d_in[6];
    const int*   ei  = (const int*)d_in[7];
    const int*   pe  = (const int*)d_in[8];
    float* out = (float*)d_out;

    float* hp; cudaGetSymbolAddress((void**)&hp, g_h);
    float* zp; cudaGetSymbolAddress((void**)&zp, g_z);
    __nv_bfloat16 *xh, *xl, *ah, *al, *hh, *hl, *w1h, *w1l, *w2h, *w2l;
    cudaGetSymbolAddress((void**)&xh,  g_xh);
    cudaGetSymbolAddress((void**)&xl,  g_xl);
    cudaGetSymbolAddress((void**)&ah,  g_aggh);
    cudaGetSymbolAddress((void**)&al,  g_aggl);
    cudaGetSymbolAddress((void**)&hh,  g_hh);
    cudaGetSymbolAddress((void**)&hl,  g_hl);
    cudaGetSymbolAddress((void**)&w1h, g_w1h);
    cudaGetSymbolAddress((void**)&w1l, g_w1l);
    cudaGetSymbolAddress((void**)&w2h, g_w2h);
    cudaGetSymbolAddress((void**)&w2l, g_w2l);

    cudaFuncSetAttribute(gemm_bf16_kernel,
                         cudaFuncAttributeMaxDynamicSharedMemorySize, GEMM_SMEM);

    // index normalization + CSR build
    detect_kernel<<<1, 32>>>(ei);
    zero_pred_kernel<<<(EP + 255) / 256, 256>>>(pe);
    edges_hist_kernel<<<(EE + 255) / 256, 256>>>(ei);
    scan1_kernel<<<NBLK, 1024>>>();
    scan_top_kernel<<<1, 32>>>();
    scan_add_kernel<<<NBLK, 1024>>>();
    scatter_kernel<<<(EE + 255) / 256, 256>>>();

    // operand conversion
    cvt_x_kernel<<<(NN * 32 + 255) / 256, 256>>>((const float4*)x);
    cvt_w_kernel<<<(4 * CC * CC + 255) / 256, 256>>>(W1l, W1r, W2l, W2r);

    int aggGrid = (NN + 7) / 8;
    int dotGrid = (EP + 7) / 8;

    // layer 1: h = relu(agg(x) @ W1l + x @ W1r + b1)
    agg_kernel<<<aggGrid, 256>>>((const float4*)x);
    gemm_bf16_kernel<<<GEMM_GRID, 256, GEMM_SMEM>>>(ah, al, xh, xl, w1h, w1l,
                                                    b1, hp, hh, hl, 1);

    // layer 2: z = agg(h) @ W2l + h @ W2r + b2
    agg_kernel<<<aggGrid, 256>>>((const float4*)hp);
    gemm_bf16_kernel<<<GEMM_GRID, 256, GEMM_SMEM>>>(ah, al, hh, hl, w2h, w2l,
                                                    b2, zp, (__nv_bfloat16*)0,
                                                    (__nv_bfloat16*)0, 0);

    // logits
    dot_kernel<<<dotGrid, 256>>>((const float4*)zp, out);
}

// round 10
// speedup vs baseline: 1.0746x; 1.0746x over previous
#include <cuda_runtime.h>
#include <cuda_bf16.h>
#include <cstdint>

#define NN   50000
#define EE   800000
#define EP   200000
#define CC   128
#define NBLK 49                      // ceil(NN/1024)
#define GEMM_GRID ((NN + 127) / 128) // 391

// ------------------------- static device scratch -------------------------
__device__ int   g_src[EE];
__device__ int   g_dst[EE];
__device__ int   g_ps[EP];
__device__ int   g_pd[EP];
__device__ int   g_deg[NN];
__device__ int   g_off[NN];
__device__ int   g_cur[NN];
__device__ int   g_bsum[64];
__device__ int   g_csr[EE];
__device__ float g_agg[NN * CC];
__device__ float g_h[NN * CC];
__device__ float g_z[NN * CC];

// ------------------------- helpers -------------------------
__device__ __forceinline__ int probe_is64(const int* p) {
    // int64 little-endian values < 50000 => odd 32-bit words are all zero.
    int ok = 1;
    #pragma unroll
    for (int i = 0; i < 16; i++) ok &= (p[2 * i + 1] == 0);
    return ok;
}

// ------------------------- zero degrees -------------------------
__global__ void zero_kernel() {
    int i = blockIdx.x * blockDim.x + threadIdx.x;
    if (i < NN) g_deg[i] = 0;
}

// probe dtype + convert edges & pred edges + histogram (one pass over EE)
__global__ void prep_kernel(const int* __restrict__ ei, const int* __restrict__ pe) {
    __shared__ int s_is64;
    if (threadIdx.x == 0) s_is64 = probe_is64(ei);
    __syncthreads();
    int is64 = s_is64;
    int e = blockIdx.x * blockDim.x + threadIdx.x;
    if (e < EP) {
        if (is64) {
            const long long* q = (const long long*)pe;
            g_ps[e] = (int)q[e];
            g_pd[e] = (int)q[EP + e];
        } else {
            g_ps[e] = pe[e];
            g_pd[e] = pe[EP + e];
        }
    }
    if (e < EE) {
        int s, d;
        if (is64) {
            const long long* q = (const long long*)ei;
            s = (int)q[e];
            d = (int)q[EE + e];
        } else {
            s = ei[e];
            d = ei[EE + e];
        }
        g_src[e] = s;
        g_dst[e] = d;
        atomicAdd(&g_deg[d], 1);
    }
}

// ------------------------- multi-block scan -------------------------
__global__ void scan1_kernel() {
    __shared__ int wsum[32];
    int b = blockIdx.x, t = threadIdx.x, i = b * 1024 + t;
    int lane = t & 31, w = t >> 5;
    int v = (i < NN) ? g_deg[i] : 0;
    int x = v;
    #pragma unroll
    for (int o = 1; o < 32; o <<= 1) {
        int y = __shfl_up_sync(0xffffffffu, x, o);
        if (lane >= o) x += y;
    }
    if (lane == 31) wsum[w] = x;
    __syncthreads();
    if (w == 0) {
        int s = wsum[lane];
        #pragma unroll
        for (int o = 1; o < 32; o <<= 1) {
            int y = __shfl_up_sync(0xffffffffu, s, o);
            if (lane >= o) s += y;
        }
        wsum[lane] = s;
    }
    __syncthreads();
    int incl = x + (w ? wsum[w - 1] : 0);
    if (i < NN) g_off[i] = incl - v;        // block-local exclusive
    if (t == 1023) g_bsum[b] = incl;
}

// add block prefixes (each block rescans the 49 block sums locally)
__global__ void scan_add_kernel() {
    __shared__ int bs[64];
    int t = threadIdx.x;
    if (t < 64) bs[t] = (t < NBLK) ? g_bsum[t] : 0;
    __syncthreads();
    if (t < 64) {
        #pragma unroll
        for (int o = 1; o < 64; o <<= 1) {
            int y = (t >= o) ? bs[t - o] : 0;
            __syncthreads();
            bs[t] += y;
            __syncthreads();
        }
    } else {
        #pragma unroll
        for (int o = 1; o < 64; o <<= 1) { __syncthreads(); __syncthreads(); }
    }
    int b = blockIdx.x;
    int pref = (b > 0) ? bs[b - 1] : 0;
    int i = b * 1024 + t;
    if (i < NN) {
        int o = g_off[i] + pref;
        g_off[i] = o;
        g_cur[i] = o;
    }
}

__global__ void scatter_kernel() {
    int e = blockIdx.x * blockDim.x + threadIdx.x;
    if (e < EE) {
        int p = atomicAdd(&g_cur[g_dst[e]], 1);
        g_csr[p] = g_src[e];
    }
}

// ------------------------- mean aggregation (pull, warp per node) -------------------------
__global__ void agg_kernel(const float4* __restrict__ in, float4* __restrict__ out) {
    int node = blockIdx.x * (blockDim.x >> 5) + (threadIdx.x >> 5);
    int lane = threadIdx.x & 31;
    if (node >= NN) return;
    int s = g_off[node];
    int d = g_deg[node];
    float4 acc = make_float4(0.f, 0.f, 0.f, 0.f);
    for (int base = 0; base < d; base += 32) {
        int cnt = min(32, d - base);
        int myidx = (lane < cnt) ? g_csr[s + base + lane] : 0;
        for (int i = 0; i < cnt; i++) {
            int src = __shfl_sync(0xffffffffu, myidx, i);
            float4 v = in[src * 32 + lane];
            acc.x += v.x; acc.y += v.y; acc.z += v.z; acc.w += v.w;
        }
    }
    float inv = (d > 0) ? (1.0f / (float)d) : 0.0f;
    acc.x *= inv; acc.y *= inv; acc.z *= inv; acc.w *= inv;
    out[node * 32 + lane] = acc;
}

// ------------------------- mma.sync split-bf16 GEMM -------------------------
// out[128x128 tile] = relu?(A1@W1 + A2@W2 + b), fp32 in/out.
// fp32 -> bf16 hi/lo; 3 HMMA passes (hi*hi + hi*lo + lo*hi).
// 256 threads = 8 warps (4 along M x 2 along N); warp tile 32x64.
#define A_STRIDE 72
#define B_STRIDE 136
#define SM_AH 0
#define SM_AL (128 * A_STRIDE * 2)                 // 18432
#define SM_BH (2 * 128 * A_STRIDE * 2)             // 36864
#define SM_BL (SM_BH + 64 * B_STRIDE * 2)          // 54272
#define GEMM_SMEM (SM_BL + 64 * B_STRIDE * 2)      // 71680

__device__ __forceinline__ void ldsm4(uint32_t* r, uint32_t addr) {
    asm volatile("ldmatrix.sync.aligned.m8n8.x4.shared.b16 {%0,%1,%2,%3}, [%4];"
                 : "=r"(r[0]), "=r"(r[1]), "=r"(r[2]), "=r"(r[3]) : "r"(addr));
}
__device__ __forceinline__ void ldsm4t(uint32_t* r, uint32_t addr) {
    asm volatile("ldmatrix.sync.aligned.m8n8.x4.trans.shared.b16 {%0,%1,%2,%3}, [%4];"
                 : "=r"(r[0]), "=r"(r[1]), "=r"(r[2]), "=r"(r[3]) : "r"(addr));
}
__device__ __forceinline__ void mma_bf16(float* d, const uint32_t* a,
                                         uint32_t b0, uint32_t b1) {
    asm volatile(
        "mma.sync.aligned.m16n8k16.row.col.f32.bf16.bf16.f32 "
        "{%0,%1,%2,%3}, {%4,%5,%6,%7}, {%8,%9}, {%0,%1,%2,%3};"
        : "+f"(d[0]), "+f"(d[1]), "+f"(d[2]), "+f"(d[3])
        : "r"(a[0]), "r"(a[1]), "r"(a[2]), "r"(a[3]), "r"(b0), "r"(b1));
}
__device__ __forceinline__ void cvt_hilo(float v, uint32_t& h, uint32_t& l) {
    __nv_bfloat16 hb = __float2bfloat16_rn(v);
    __nv_bfloat16 lb = __float2bfloat16_rn(v - __bfloat162float(hb));
    h = (uint32_t)__bfloat16_as_ushort(hb);
    l = (uint32_t)__bfloat16_as_ushort(lb);
}

__global__ __launch_bounds__(256, 2)
void gemm_mma_kernel(const float* __restrict__ A1, const float* __restrict__ A2,
                     const float* __restrict__ W1, const float* __restrict__ W2,
                     const float* __restrict__ bias, float* __restrict__ out,
                     int do_relu) {
    extern __shared__ char sm[];
    uint32_t smb = (uint32_t)__cvta_generic_to_shared(sm);
    __nv_bfloat16* AsH = (__nv_bfloat16*)(sm + SM_AH);
    __nv_bfloat16* AsL = (__nv_bfloat16*)(sm + SM_AL);
    __nv_bfloat16* BsH = (__nv_bfloat16*)(sm + SM_BH);
    __nv_bfloat16* BsL = (__nv_bfloat16*)(sm + SM_BL);

    int tid = threadIdx.x;
    int wid = tid >> 5, lane = tid & 31;
    int warpM = wid & 3;          // 0..3 -> 32 rows each
    int warpN = wid >> 2;         // 0..1 -> 64 cols each
    int rowBase = blockIdx.x * 128;

    float acc[64];
    #pragma unroll
    for (int i = 0; i < 64; i++) acc[i] = 0.f;

    // 4 K-chunks of 64: chunks 0,1 -> (A1,W1); chunks 2,3 -> (A2,W2)
    for (int c = 0; c < 4; c++) {
        const float* A = (c < 2) ? A1 : A2;
        const float* W = (c < 2) ? W1 : W2;
        int k0 = (c & 1) * 64;

        __syncthreads();   // previous chunk's compute done before overwrite

        // A chunk: 128 rows x 64 k fp32 -> hi/lo bf16
        #pragma unroll
        for (int it = 0; it < 8; it++) {
            int idx = it * 256 + tid;
            int r = idx >> 4;          // 0..127
            int q = idx & 15;          // float4 within 64 k
            float4 v = make_float4(0.f, 0.f, 0.f, 0.f);
            int grow = rowBase + r;
            if (grow < NN) v = *(const float4*)&A[grow * CC + k0 + q * 4];
            uint32_t h0, l0, h1, l1, h2, l2, h3, l3;
            cvt_hilo(v.x, h0, l0); cvt_hilo(v.y, h1, l1);
            cvt_hilo(v.z, h2, l2); cvt_hilo(v.w, h3, l3);
            uint2 uh, ul;
            uh.x = h0 | (h1 << 16); uh.y = h2 | (h3 << 16);
            ul.x = l0 | (l1 << 16); ul.y = l2 | (l3 << 16);
            *(uint2*)&AsH[r * A_STRIDE + q * 4] = uh;
            *(uint2*)&AsL[r * A_STRIDE + q * 4] = ul;
        }
        // B chunk: 64 k-rows x 128 n fp32 -> hi/lo bf16
        #pragma unroll
        for (int it = 0; it < 8; it++) {
            int idx = it * 256 + tid;
            int kr = idx >> 5;         // 0..63
            int nq = idx & 31;         // float4 along n
            float4 v = *(const float4*)&W[(k0 + kr) * CC + nq * 4];
            uint32_t h0, l0, h1, l1, h2, l2, h3, l3;
            cvt_hilo(v.x, h0, l0); cvt_hilo(v.y, h1, l1);
            cvt_hilo(v.z, h2, l2); cvt_hilo(v.w, h3, l3);
            uint2 uh, ul;
            uh.x = h0 | (h1 << 16); uh.y = h2 | (h3 << 16);
            ul.x = l0 | (l1 << 16); ul.y = l2 | (l3 << 16);
            *(uint2*)&BsH[kr * B_STRIDE + nq * 4] = uh;
            *(uint2*)&BsL[kr * B_STRIDE + nq * 4] = ul;
        }
        __syncthreads();

        // compute: 4 k-steps of 16
        #pragma unroll
        for (int ks = 0; ks < 4; ks++) {
            int kk = ks * 16;
            uint32_t ah[2][4], al[2][4];
            int r16 = lane & 15, cb = lane >> 4;
            #pragma unroll
            for (int mf = 0; mf < 2; mf++) {
                uint32_t off = (uint32_t)(warpM * 32 + mf * 16 + r16) * (A_STRIDE * 2)
                             + (uint32_t)(kk + cb * 8) * 2;
                ldsm4(ah[mf], smb + SM_AH + off);
                ldsm4(al[mf], smb + SM_AL + off);
            }
            int brow = kk + (lane & 7) + ((lane >> 3) & 1) * 8;
            #pragma unroll
            for (int np = 0; np < 4; np++) {
                int n0 = warpN * 64 + np * 16 + (lane >> 4) * 8;
                uint32_t boff = (uint32_t)brow * (B_STRIDE * 2) + (uint32_t)n0 * 2;
                uint32_t bh[4], bl[4];
                ldsm4t(bh, smb + SM_BH + boff);
                ldsm4t(bl, smb + SM_BL + boff);
                #pragma unroll
                for (int mf = 0; mf < 2; mf++) {
                    float* d0 = &acc[(mf * 8 + np * 2 + 0) * 4];
                    float* d1 = &acc[(mf * 8 + np * 2 + 1) * 4];
                    mma_bf16(d0, ah[mf], bh[0], bh[1]);
                    mma_bf16(d1, ah[mf], bh[2], bh[3]);
                    mma_bf16(d0, ah[mf], bl[0], bl[1]);
                    mma_bf16(d1, ah[mf], bl[2], bl[3]);
                    mma_bf16(d0, al[mf], bh[0], bh[1]);
                    mma_bf16(d1, al[mf], bh[2], bh[3]);
                }
            }
        }
    }

    // epilogue: bias + optional relu, float2 stores
    int r = lane >> 2;
    int cb2 = (lane & 3) * 2;
    #pragma unroll
    for (int mf = 0; mf < 2; mf++) {
        int row0 = rowBase + warpM * 32 + mf * 16 + r;
        #pragma unroll
        for (int np = 0; np < 4; np++) {
            #pragma unroll
            for (int half = 0; half < 2; half++) {
                int col = warpN * 64 + np * 16 + half * 8 + cb2;
                const float* d = &acc[(mf * 8 + np * 2 + half) * 4];
                float bx = __ldg(&bias[col]);
                float by = __ldg(&bias[col + 1]);
                float2 o0, o1;
                o0.x = d[0] + bx; o0.y = d[1] + by;
                o1.x = d[2] + bx; o1.y = d[3] + by;
                if (do_relu) {
                    o0.x = fmaxf(o0.x, 0.f); o0.y = fmaxf(o0.y, 0.f);
                    o1.x = fmaxf(o1.x, 0.f); o1.y = fmaxf(o1.y, 0.f);
                }
                if (row0 < NN)     *(float2*)&out[row0 * CC + col] = o0;
                if (row0 + 8 < NN) *(float2*)&out[(row0 + 8) * CC + col] = o1;
            }
        }
    }
}

// ------------------------- link prediction dot -------------------------
__global__ void dot_kernel(const float4* __restrict__ z, float* __restrict__ out) {
    int e = blockIdx.x * (blockDim.x >> 5) + (threadIdx.x >> 5);
    int lane = threadIdx.x & 31;
    if (e >= EP) return;
    int a = g_ps[e];
    int b = g_pd[e];
    float4 va = z[a * 32 + lane];
    float4 vb = z[b * 32 + lane];
    float s = va.x * vb.x + va.y * vb.y + va.z * vb.z + va.w * vb.w;
    #pragma unroll
    for (int o = 16; o > 0; o >>= 1) s += __shfl_xor_sync(0xffffffffu, s, o);
    if (lane == 0) out[e] = s;
}

// ------------------------- launch -------------------------
extern "C" void kernel_launch(void* const* d_in, const int* in_sizes, int n_in,
                              void* d_out, int out_size) {
    const float* x   = (const float*)d_in[0];
    const float* W1l = (const float*)d_in[1];
    const float* b1  = (const float*)d_in[2];
    const float* W1r = (const float*)d_in[3];
    const float* W2l = (const float*)d_in[4];
    const float* b2  = (const float*)d_in[5];
    const float* W2r = (const float*)d_in[6];
    const int*   ei  = (const int*)d_in[7];
    const int*   pe  = (const int*)d_in[8];
    float* out = (float*)d_out;

    float* aggp; cudaGetSymbolAddress((void**)&aggp, g_agg);
    float* hp;   cudaGetSymbolAddress((void**)&hp,   g_h);
    float* zp;   cudaGetSymbolAddress((void**)&zp,   g_z);

    cudaFuncSetAttribute(gemm_mma_kernel,
                         cudaFuncAttributeMaxDynamicSharedMemorySize, GEMM_SMEM);

    // CSR build (4 kernels + zero)
    zero_kernel<<<(NN + 255) / 256, 256>>>();                    // 0
    prep_kernel<<<(EE + 255) / 256, 256>>>(ei, pe);              // 1
    scan1_kernel<<<NBLK, 1024>>>();                              // 2
    scan_add_kernel<<<NBLK, 1024>>>();                           // 3
    scatter_kernel<<<(EE + 255) / 256, 256>>>();                 // 4

    int aggGrid = (NN + 7) / 8;
    int dotGrid = (EP + 7) / 8;

    // layer 1: h = relu(agg(x) @ W1l + x @ W1r + b1)
    agg_kernel<<<aggGrid, 256>>>((const float4*)x, (float4*)aggp);        // 5 (profiled)
    gemm_mma_kernel<<<GEMM_GRID, 256, GEMM_SMEM>>>(aggp, x, W1l, W1r, b1, hp, 1);

    // layer 2: z = agg(h) @ W2l + h @ W2r + b2
    agg_kernel<<<aggGrid, 256>>>((const float4*)hp, (float4*)aggp);
    gemm_mma_kernel<<<GEMM_GRID, 256, GEMM_SMEM>>>(aggp, hp, W2l, W2r, b2, zp, 0);

    // logits
    dot_kernel<<<dotGrid, 256>>>((const float4*)zp, out);
}